// round 7
// baseline (speedup 1.0000x reference)
#include <cuda_runtime.h>
#include <cstdint>

#define TT 1024
#define BB 128
#define CC 256
#define SS 128
#define NTHR 128        // 4 warps, 1 per SMSP
#define WIN 16          // steps per sync window (overlap 84 supports 21)
#define LOG2E 1.4426950408889634f
#define LN2F  0.6931471805599453f
#define NEG2  (-1.0e9f)

__device__ float g_loss[BB];
__device__ int   g_done;          // zero-init; nets to zero every launch

static __device__ __forceinline__ float fexp2(float x){ float y; asm("ex2.approx.ftz.f32 %0, %1;" : "=f"(y) : "f"(x)); return y; }
static __device__ __forceinline__ float flog2(float x){ float y; asm("lg2.approx.f32 %0, %1;" : "=f"(y) : "f"(x)); return y; }
static __device__ __forceinline__ void cp16(unsigned dst, const float* src){
  asm volatile("cp.async.cg.shared.global [%0], [%1], 16;" :: "r"(dst), "l"(src));
}
static __device__ __forceinline__ void cp_commit(){ asm volatile("cp.async.commit_group;"); }
template<int N> static __device__ __forceinline__ void cp_wait(){ asm volatile("cp.async.wait_group %0;" :: "n"(N)); }

__global__ void __launch_bounds__(NTHR, 1) ctc_fwd(
    const float* __restrict__ lp, const int* __restrict__ y,
    const int* __restrict__ ilen, const int* __restrict__ tlen,
    float* __restrict__ out)
{
  __shared__ __align__(16) float rows[2 * WIN][CC]; // 32KB emission row ring, 2 windows
  __shared__ float alphA[264];                      // alpha exchange, double-buffered
  __shared__ float alphB[264];
  __shared__ float red[4];
  __shared__ int   lastblk;

  const int b    = blockIdx.x;
  const int tid  = threadIdx.x;
  const int w    = tid >> 5;
  const int lane = tid & 31;
  const int len  = ilen[b];
  const int tl   = tlen[b];

  // Lane layout: warp strip base 44*w; lane holds 4 consecutive states sb..sb+3
  const int sb = 44 * w + 4 * lane;      // even
  // owned partition tiling [0,260): w0 [0,86), w1 [86,130), w2 [130,174), w3 [174,260)
  const int ow_lo = w ? 44 * w + 42 : 0;
  const int ow_hi = (w < 3) ? 44 * (w + 1) + 42 : 260;
  const bool p0 = (sb     >= ow_lo) & (sb     < ow_hi);
  const bool p1 = (sb + 1 >= ow_lo) & (sb + 1 < ow_hi);
  const bool p2 = (sb + 2 >= ow_lo) & (sb + 2 < ow_hi);
  const bool p3 = (sb + 3 >= ow_lo) & (sb + 3 < ow_hi);
  const bool lowcut = (w == 0) & (lane == 0);   // state 0 has no s-1

  // labels for odd states sb+1 (idx i1) and sb+3 (idx i1+1)
  const int i1 = sb >> 1;
  const int i3 = i1 + 1;
  const int i1c = i1 < SS ? i1 : SS - 1;
  const int i3c = i3 < SS ? i3 : SS - 1;
  const int cls1 = y[b * SS + i1c];
  const int cls3 = y[b * SS + i3c];
  const bool sk1 = (i1 >= 1) && (i1 < SS) && (cls1 != y[b * SS + i1c - 1]);
  const bool sk3 = (i3 < SS) && (cls3 != cls1);

  const float* gb = lp + (size_t)b * CC;
  const unsigned rows_u = (unsigned)__cvta_generic_to_shared(&rows[0][0]);

  // issue one 16-row window as one commit group (1024 coalesced 16B chunks)
  auto issue_win = [&](int wt) {
    int bslot = ((wt / WIN) & 1) * WIN;
    #pragma unroll
    for (int k = 0; k < 8; ++k) {
      int c = tid + k * NTHR;            // 0..1023
      int r   = c >> 6;
      int off = (c & 63) * 16;
      int row = wt + r;
      if (row < TT)
        cp16(rows_u + (unsigned)((bslot + r) * (CC * 4) + off),
             gb + (size_t)row * (BB * CC) + (off >> 2));
    }
    cp_commit();
  };

  issue_win(0);
  cp_wait<0>();
  __syncthreads();

  // t=0 init: only global states 0 and 1 reachable (w0 lane0)
  float a0 = NEG2, a1 = NEG2, a2 = NEG2, a3 = NEG2;
  if (lowcut) {
    a0 = rows[0][0]    * LOG2E;
    a1 = rows[0][cls1] * LOG2E;
  }

  int wi = 0;
  for (int wt = 0; wt < len; wt += WIN, ++wi) {
    float* cur = (wi & 1) ? alphB : alphA;
    const int ws = (wi & 1) * WIN;

    // publish owned alpha_(wt-1) (t=0 init for window 0)
    if (p0) cur[sb]     = a0;
    if (p1) cur[sb + 1] = a1;
    if (p2) cur[sb + 2] = a2;
    if (p3) cur[sb + 3] = a3;

    cp_wait<0>();              // window wi resident
    __syncthreads();           // alpha publish + rows visibility

    issue_win(wt + WIN);       // other slot; its readers passed the barrier above

    // refresh strip (fresh halo via neighbors' owned partitions)
    a0 = cur[sb];
    a1 = cur[sb + 1];
    a2 = cur[sb + 2];
    a3 = cur[sb + 3];

    // preload emissions for the whole window into registers (off the step chain)
    float eB[WIN], e1[WIN], e3[WIN];
    #pragma unroll
    for (int j = 0; j < WIN; ++j) {
      eB[j] = rows[ws + j][0]    * LOG2E;
      e1[j] = rows[ws + j][cls1] * LOG2E;
      e3[j] = rows[ws + j][cls3] * LOG2E;
    }

    #pragma unroll
    for (int j = 0; j < WIN; ++j) {
      const int t = wt + j;
      if (t >= 1 && t < len) {
        float sh = __shfl_up_sync(0xffffffffu, a3, 1);  // left lane's top state
        sh = lowcut ? NEG2 : sh;
        // s0 even: lse2(a0, sh)
        float m0 = fmaxf(a0, sh);
        float n0 = fminf(a0, sh);
        float r0 = m0 + flog2(1.0f + fexp2(n0 - m0)) + eB[j];
        // s1 odd: lse3(a1, a0, sh if skip)
        float x1 = sk1 ? sh : NEG2;
        float m1 = fmaxf(a1, fmaxf(a0, x1));
        float r1 = m1 + flog2(fexp2(a1 - m1) + fexp2(a0 - m1) + fexp2(x1 - m1)) + e1[j];
        // s2 even: lse2(a2, a1)
        float m2 = fmaxf(a2, a1);
        float n2 = fminf(a2, a1);
        float r2 = m2 + flog2(1.0f + fexp2(n2 - m2)) + eB[j];
        // s3 odd: lse3(a3, a2, a1 if skip)
        float x3 = sk3 ? a1 : NEG2;
        float m3 = fmaxf(a3, fmaxf(a2, x3));
        float r3 = m3 + flog2(fexp2(a3 - m3) + fexp2(a2 - m3) + fexp2(x3 - m3)) + e3[j];
        a0 = r0; a1 = r1; a2 = r2; a3 = r3;
      }
    }
  }

  // final: stage alpha_(len-1), extract loss
  __syncthreads();
  if (p0) alphA[sb]     = a0;
  if (p1) alphA[sb + 1] = a1;
  if (p2) alphA[sb + 2] = a2;
  if (p3) alphA[sb + 3] = a3;
  __syncthreads();

  if (tid == 0) {
    float ahi = alphA[2 * tl];
    float alo = alphA[2 * tl - 1];
    float m  = fmaxf(ahi, alo);
    float mn = fminf(ahi, alo);
    float ll2 = m + flog2(1.0f + fexp2(mn - m));
    float loss = -ll2 * LN2F;
    if (!(loss < 0.5e9f)) loss = 0.f;    // zero_infinity (also inf/nan)
    g_loss[b] = loss / (float)tl;
    __threadfence();
    int old = atomicAdd(&g_done, 1);
    int isl = (old == BB - 1);
    if (isl) g_done = 0;                 // reset for next graph replay
    lastblk = isl;
  }
  __syncthreads();

  if (lastblk) {                         // fused mean over batches in last block
    __threadfence();
    float v = g_loss[tid];               // NTHR == BB == 128
    #pragma unroll
    for (int o = 16; o > 0; o >>= 1) v += __shfl_down_sync(0xffffffffu, v, o);
    if (lane == 0) red[w] = v;
    __syncthreads();
    if (tid == 0) out[0] = (red[0] + red[1] + red[2] + red[3]) * (1.0f / (float)BB);
  }
}

extern "C" void kernel_launch(void* const* d_in, const int* in_sizes, int n_in,
                              void* d_out, int out_size)
{
  const float* lp = (const float*)d_in[0];
  const int*   yy = (const int*)  d_in[1];
  const int*   il = (const int*)  d_in[2];
  const int*   tl = (const int*)  d_in[3];
  ctc_fwd<<<BB, NTHR>>>(lp, yy, il, tl, (float*)d_out);
}